// round 1
// baseline (speedup 1.0000x reference)
#include <cuda_runtime.h>
#include <math.h>

// ---------------- problem constants ----------------
#define S_LEN   2048
#define HID     4096
#define QKV_N   12288
#define D_HEAD  128
#define DV      256
#define HP_N    16
#define LAMBDA_INIT 0.35550906759096926f   // 0.8 - 0.6*exp(-0.3)
#define EPS     1e-5f

// ---------------- scratch (no allocations allowed) ----------------
__device__ float g_qkv[(size_t)S_LEN * QKV_N];   // 100.7 MB
__device__ float g_attn1[(size_t)S_LEN * HID];   // 33.5 MB
__device__ float g_attn2[(size_t)S_LEN * HID];   // 33.5 MB
__device__ float g_x[(size_t)S_LEN * HID];       // 33.5 MB
__device__ float g_lambda;

// ---------------- SGEMM: C[M,N] = A[M,K] * B[N,K]^T + bias[N] ----------------
// BM=BN=128, BK=8, 256 threads, 8x8 micro-tile per thread.
__global__ __launch_bounds__(256)
void sgemm_nt_128(const float* __restrict__ A, const float* __restrict__ B,
                  const float* __restrict__ bias, float* __restrict__ C,
                  int M, int N, int K)
{
    __shared__ float As[8][132];
    __shared__ float Bs[8][132];

    const int tid = threadIdx.x;
    const int tr  = tid >> 4;          // 0..15
    const int tc  = tid & 15;          // 0..15
    const int row0 = blockIdx.y * 128 + tr * 8;
    const int col0 = blockIdx.x * 128 + tc * 8;

    const int lRow = tid >> 1;         // 0..127
    const int lK   = (tid & 1) * 4;    // 0 or 4
    const float* Ap = A + (size_t)(blockIdx.y * 128 + lRow) * K + lK;
    const float* Bp = B + (size_t)(blockIdx.x * 128 + lRow) * K + lK;

    float acc[8][8];
#pragma unroll
    for (int i = 0; i < 8; i++)
#pragma unroll
        for (int j = 0; j < 8; j++) acc[i][j] = 0.f;

    for (int kt = 0; kt < K; kt += 8) {
        float4 av = *(const float4*)(Ap + kt);
        float4 bv = *(const float4*)(Bp + kt);
        As[lK + 0][lRow] = av.x; As[lK + 1][lRow] = av.y;
        As[lK + 2][lRow] = av.z; As[lK + 3][lRow] = av.w;
        Bs[lK + 0][lRow] = bv.x; Bs[lK + 1][lRow] = bv.y;
        Bs[lK + 2][lRow] = bv.z; Bs[lK + 3][lRow] = bv.w;
        __syncthreads();
#pragma unroll
        for (int k = 0; k < 8; k++) {
            float ra[8], rb[8];
            *(float4*)&ra[0] = *(const float4*)&As[k][tr * 8];
            *(float4*)&ra[4] = *(const float4*)&As[k][tr * 8 + 4];
            *(float4*)&rb[0] = *(const float4*)&Bs[k][tc * 8];
            *(float4*)&rb[4] = *(const float4*)&Bs[k][tc * 8 + 4];
#pragma unroll
            for (int i = 0; i < 8; i++)
#pragma unroll
                for (int j = 0; j < 8; j++)
                    acc[i][j] = fmaf(ra[i], rb[j], acc[i][j]);
        }
        __syncthreads();
    }

#pragma unroll
    for (int i = 0; i < 8; i++) {
        float* Cp = C + (size_t)(row0 + i) * N + col0;
#pragma unroll
        for (int j = 0; j < 8; j++) Cp[j] = acc[i][j] + bias[col0 + j];
    }
}

// ---------------- lambda scalar ----------------
__global__ void lambda_kernel(const float* __restrict__ q1, const float* __restrict__ k1,
                              const float* __restrict__ q2, const float* __restrict__ k2)
{
    const int tid = threadIdx.x;   // 128 threads
    float p1 = q1[tid] * k1[tid];
    float p2 = q2[tid] * k2[tid];
#pragma unroll
    for (int m = 16; m; m >>= 1) {
        p1 += __shfl_xor_sync(0xffffffffu, p1, m);
        p2 += __shfl_xor_sync(0xffffffffu, p2, m);
    }
    __shared__ float s1[4], s2[4];
    if ((tid & 31) == 0) { s1[tid >> 5] = p1; s2[tid >> 5] = p2; }
    __syncthreads();
    if (tid == 0) {
        float a = s1[0] + s1[1] + s1[2] + s1[3];
        float b = s2[0] + s2[1] + s2[2] + s2[3];
        g_lambda = expf(a) - expf(b) + LAMBDA_INIT;
    }
}

// ---------------- causal flash attention (fp32) ----------------
// grid: (S/64, HP, 2). block 256. Each block: 64 q-rows, one head-pair,
// one of the two q/k halves (a=blockIdx.z). Output 256-wide (full v12).
__global__ __launch_bounds__(256)
void diff_attn(const float* __restrict__ qkv,
               float* __restrict__ out1, float* __restrict__ out2)
{
    extern __shared__ float sm[];
    float* Qs   = sm;                 // [128][64]  d-major
    float* KV   = Qs + 128 * 64;      // K: [128][64] d-major, then reused as V: [64][256]
    float* Ps   = KV + 64 * 256;      // [64][64]
    float* mrow = Ps + 64 * 64;       // [64]
    float* lrow = mrow + 64;          // [64]
    float* crow = lrow + 64;          // [64]
    float* tmax = crow + 64;          // [64]
    float* tsum = tmax + 64;          // [64]

    const int tid = threadIdx.x;
    const int qi  = blockIdx.x;
    const int hp  = blockIdx.y;
    const int a   = blockIdx.z;
    const int q0  = qi * 64;
    const int qoff = hp * 256 + a * 128;
    const int koff = HID + qoff;
    const int voff = 2 * HID + hp * 256;
    float* out = a ? out2 : out1;

    // load Q tile transposed: Qs[d][r]
    for (int i = tid; i < 64 * 32; i += 256) {
        int r = i >> 5; int d = (i & 31) << 2;
        float4 v = *(const float4*)&qkv[(size_t)(q0 + r) * QKV_N + qoff + d];
        Qs[(d + 0) * 64 + r] = v.x; Qs[(d + 1) * 64 + r] = v.y;
        Qs[(d + 2) * 64 + r] = v.z; Qs[(d + 3) * 64 + r] = v.w;
    }
    if (tid < 64) { mrow[tid] = -1e30f; lrow[tid] = 0.f; }

    const int tr = tid >> 4, tc = tid & 15;
    const int r0 = tr * 4, cs0 = tc * 4, cv0 = tc * 16;
    float oacc[4][16];
#pragma unroll
    for (int i = 0; i < 4; i++)
#pragma unroll
        for (int j = 0; j < 16; j++) oacc[i][j] = 0.f;
    __syncthreads();

    const float scale = 0.088388347648318447f;  // 1/sqrt(128)
    const int ntiles = qi + 1;

    for (int t = 0; t < ntiles; t++) {
        const int k0 = t * 64;

        // load K tile transposed: KV[d][c]
        for (int i = tid; i < 64 * 32; i += 256) {
            int c = i >> 5; int d = (i & 31) << 2;
            float4 v = *(const float4*)&qkv[(size_t)(k0 + c) * QKV_N + koff + d];
            KV[(d + 0) * 64 + c] = v.x; KV[(d + 1) * 64 + c] = v.y;
            KV[(d + 2) * 64 + c] = v.z; KV[(d + 3) * 64 + c] = v.w;
        }
        __syncthreads();

        // S = Q K^T (4x4 per thread)
        float s4[4][4];
#pragma unroll
        for (int i = 0; i < 4; i++)
#pragma unroll
            for (int j = 0; j < 4; j++) s4[i][j] = 0.f;
#pragma unroll 4
        for (int d = 0; d < 128; d++) {
            float qa[4], kb[4];
            *(float4*)qa = *(const float4*)&Qs[d * 64 + r0];
            *(float4*)kb = *(const float4*)&KV[d * 64 + cs0];
#pragma unroll
            for (int i = 0; i < 4; i++)
#pragma unroll
                for (int j = 0; j < 4; j++)
                    s4[i][j] = fmaf(qa[i], kb[j], s4[i][j]);
        }
        __syncthreads();   // done reading K from KV

        // overlap: load V tile into KV (natural layout [j][e])
        for (int i = tid; i < 64 * 64; i += 256) {
            int j = i >> 6; int e = (i & 63) << 2;
            *(float4*)&KV[j * 256 + e] =
                *(const float4*)&qkv[(size_t)(k0 + j) * QKV_N + voff + e];
        }

        // scale + causal mask + tile row-max
        const bool diag = (t == qi);
        float rm[4];
#pragma unroll
        for (int i = 0; i < 4; i++) {
            rm[i] = -1e30f;
#pragma unroll
            for (int j = 0; j < 4; j++) {
                float v = s4[i][j] * scale;
                if (diag && (k0 + cs0 + j) > (q0 + r0 + i)) v = -1e30f;
                s4[i][j] = v;
                rm[i] = fmaxf(rm[i], v);
            }
        }
#pragma unroll
        for (int m = 1; m < 16; m <<= 1)
#pragma unroll
            for (int i = 0; i < 4; i++)
                rm[i] = fmaxf(rm[i], __shfl_xor_sync(0xffffffffu, rm[i], m, 32));
        if (tc == 0) {
            tmax[r0 + 0] = rm[0]; tmax[r0 + 1] = rm[1];
            tmax[r0 + 2] = rm[2]; tmax[r0 + 3] = rm[3];
        }
        __syncthreads();

        // online softmax stats update (one thread per row)
        if (tid < 64) {
            float mo = mrow[tid];
            float mn = fmaxf(mo, tmax[tid]);
            float c  = __expf(mo - mn);
            mrow[tid] = mn; crow[tid] = c; lrow[tid] *= c;
        }
        __syncthreads();

        // P = exp(S - m), write to shared; rescale O; tile row-sum
        float rs[4];
#pragma unroll
        for (int i = 0; i < 4; i++) {
            const float mn = mrow[r0 + i];
            rs[i] = 0.f;
#pragma unroll
            for (int j = 0; j < 4; j++) {
                float p = __expf(s4[i][j] - mn);
                Ps[(r0 + i) * 64 + cs0 + j] = p;
                rs[i] += p;
            }
            const float c = crow[r0 + i];
#pragma unroll
            for (int e = 0; e < 16; e++) oacc[i][e] *= c;
        }
#pragma unroll
        for (int m = 1; m < 16; m <<= 1)
#pragma unroll
            for (int i = 0; i < 4; i++)
                rs[i] += __shfl_xor_sync(0xffffffffu, rs[i], m, 32);
        if (tc == 0) {
            tsum[r0 + 0] = rs[0]; tsum[r0 + 1] = rs[1];
            tsum[r0 + 2] = rs[2]; tsum[r0 + 3] = rs[3];
        }
        __syncthreads();
        if (tid < 64) lrow[tid] += tsum[tid];

        // O += P V (rows r0.., cols cv0..cv0+15)
#pragma unroll 2
        for (int j = 0; j < 64; j++) {
            float p0 = Ps[(r0 + 0) * 64 + j];
            float p1 = Ps[(r0 + 1) * 64 + j];
            float p2 = Ps[(r0 + 2) * 64 + j];
            float p3 = Ps[(r0 + 3) * 64 + j];
            const float* vp = &KV[j * 256 + cv0];
#pragma unroll
            for (int e4 = 0; e4 < 4; e4++) {
                float4 vv = *(const float4*)&vp[e4 * 4];
                oacc[0][e4 * 4 + 0] = fmaf(p0, vv.x, oacc[0][e4 * 4 + 0]);
                oacc[0][e4 * 4 + 1] = fmaf(p0, vv.y, oacc[0][e4 * 4 + 1]);
                oacc[0][e4 * 4 + 2] = fmaf(p0, vv.z, oacc[0][e4 * 4 + 2]);
                oacc[0][e4 * 4 + 3] = fmaf(p0, vv.w, oacc[0][e4 * 4 + 3]);
                oacc[1][e4 * 4 + 0] = fmaf(p1, vv.x, oacc[1][e4 * 4 + 0]);
                oacc[1][e4 * 4 + 1] = fmaf(p1, vv.y, oacc[1][e4 * 4 + 1]);
                oacc[1][e4 * 4 + 2] = fmaf(p1, vv.z, oacc[1][e4 * 4 + 2]);
                oacc[1][e4 * 4 + 3] = fmaf(p1, vv.w, oacc[1][e4 * 4 + 3]);
                oacc[2][e4 * 4 + 0] = fmaf(p2, vv.x, oacc[2][e4 * 4 + 0]);
                oacc[2][e4 * 4 + 1] = fmaf(p2, vv.y, oacc[2][e4 * 4 + 1]);
                oacc[2][e4 * 4 + 2] = fmaf(p2, vv.z, oacc[2][e4 * 4 + 2]);
                oacc[2][e4 * 4 + 3] = fmaf(p2, vv.w, oacc[2][e4 * 4 + 3]);
                oacc[3][e4 * 4 + 0] = fmaf(p3, vv.x, oacc[3][e4 * 4 + 0]);
                oacc[3][e4 * 4 + 1] = fmaf(p3, vv.y, oacc[3][e4 * 4 + 1]);
                oacc[3][e4 * 4 + 2] = fmaf(p3, vv.z, oacc[3][e4 * 4 + 2]);
                oacc[3][e4 * 4 + 3] = fmaf(p3, vv.w, oacc[3][e4 * 4 + 3]);
            }
        }
        __syncthreads();
    }

    // epilogue: divide by l, write out
#pragma unroll
    for (int i = 0; i < 4; i++) {
        const float inv = 1.f / lrow[r0 + i];
        float* op = out + (size_t)(q0 + r0 + i) * HID + hp * 256 + cv0;
#pragma unroll
        for (int e = 0; e < 16; e++) op[e] = oacc[i][e] * inv;
    }
}

// ---------------- combine (attn1 - lambda*attn2) + RMSNorm ----------------
// grid (S, HP), 256 threads — one thread per element of the 2D=256 group.
__global__ __launch_bounds__(256)
void combine_rms(const float* __restrict__ a1, const float* __restrict__ a2,
                 const float* __restrict__ w, float* __restrict__ x)
{
    const int s = blockIdx.x, hp = blockIdx.y, e = threadIdx.x;
    const size_t idx = (size_t)s * HID + hp * 256 + e;
    const float lam = g_lambda;
    const float v = a1[idx] - lam * a2[idx];
    float ss = v * v;
#pragma unroll
    for (int m = 16; m; m >>= 1) ss += __shfl_xor_sync(0xffffffffu, ss, m);
    __shared__ float red[8];
    if ((e & 31) == 0) red[e >> 5] = ss;
    __syncthreads();
    float tot = 0.f;
#pragma unroll
    for (int i = 0; i < 8; i++) tot += red[i];
    const float r = rsqrtf(tot * (1.f / 256.f) + EPS);
    x[idx] = w[e] * v * r * (1.f - LAMBDA_INIT);
}

// ---------------- launch ----------------
extern "C" void kernel_launch(void* const* d_in, const int* in_sizes, int n_in,
                              void* d_out, int out_size)
{
    const float* hidden = (const float*)d_in[0];
    const float* Wqkv_w = (const float*)d_in[1];
    const float* Wqkv_b = (const float*)d_in[2];
    const float* out_w  = (const float*)d_in[3];
    const float* out_b  = (const float*)d_in[4];
    const float* lq1    = (const float*)d_in[5];
    const float* lk1    = (const float*)d_in[6];
    const float* lq2    = (const float*)d_in[7];
    const float* lk2    = (const float*)d_in[8];
    const float* subln  = (const float*)d_in[9];
    float* out = (float*)d_out;

    float *qkv, *a1, *a2, *x;
    cudaGetSymbolAddress((void**)&qkv, g_qkv);
    cudaGetSymbolAddress((void**)&a1,  g_attn1);
    cudaGetSymbolAddress((void**)&a2,  g_attn2);
    cudaGetSymbolAddress((void**)&x,   g_x);

    const int SMEM_ATT = (128 * 64 + 64 * 256 + 64 * 64 + 5 * 64) * (int)sizeof(float);
    cudaFuncSetAttribute(diff_attn, cudaFuncAttributeMaxDynamicSharedMemorySize, SMEM_ATT);

    // 1. lambda scalar
    lambda_kernel<<<1, 128>>>(lq1, lk1, lq2, lk2);

    // 2. QKV projection: [2048,12288] = hidden[2048,4096] @ Wqkv_w[12288,4096]^T
    sgemm_nt_128<<<dim3(QKV_N / 128, S_LEN / 128), 256>>>(
        hidden, Wqkv_w, Wqkv_b, qkv, S_LEN, QKV_N, HID);

    // 3. dual causal flash attention (a=0 -> attn1, a=1 -> attn2)
    diff_attn<<<dim3(S_LEN / 64, HP_N, 2), 256, SMEM_ATT>>>(qkv, a1, a2);

    // 4. combine + rmsnorm
    combine_rms<<<dim3(S_LEN, HP_N), 256>>>(a1, a2, subln, x);

    // 5. output projection: [2048,4096] = x @ out_w[4096,4096]^T
    sgemm_nt_128<<<dim3(HID / 128, S_LEN / 128), 256>>>(
        x, out_w, out_b, out, S_LEN, HID, HID);
}

// round 2
// speedup vs baseline: 1.6854x; 1.6854x over previous
#include <cuda_runtime.h>
#include <math.h>
#include <stdint.h>

// ---------------- problem constants ----------------
#define S_LEN   2048
#define HID     4096
#define QKV_N   12288
#define D_HEAD  128
#define HP_N    16
#define LAMBDA_INIT 0.35550906759096926f   // 0.8 - 0.6*exp(-0.3)
#define EPS     1e-5f

// ---------------- scratch (no allocations allowed) ----------------
__device__ float g_qkv[(size_t)S_LEN * QKV_N];   // 100.7 MB
__device__ float g_attn1[(size_t)S_LEN * HID];   // 33.5 MB
__device__ float g_attn2[(size_t)S_LEN * HID];   // 33.5 MB
__device__ float g_x[(size_t)S_LEN * HID];       // 33.5 MB
__device__ float g_lambda;

// ---------------- tf32 helpers ----------------
__device__ __forceinline__ uint32_t f2tf32(float f) {
    uint32_t o;
    asm("cvt.rna.tf32.f32 %0, %1;" : "=r"(o) : "f"(f));
    return o;
}

__device__ __forceinline__ void mma_tf32(float4& d,
                                         const uint32_t a0, const uint32_t a1,
                                         const uint32_t a2, const uint32_t a3,
                                         const uint32_t b0, const uint32_t b1)
{
    asm volatile(
        "mma.sync.aligned.m16n8k8.row.col.f32.tf32.tf32.f32 "
        "{%0,%1,%2,%3}, {%4,%5,%6,%7}, {%8,%9}, {%0,%1,%2,%3};\n"
        : "+f"(d.x), "+f"(d.y), "+f"(d.z), "+f"(d.w)
        : "r"(a0), "r"(a1), "r"(a2), "r"(a3), "r"(b0), "r"(b1));
}

// ---------------- tensor-core GEMM (tf32): C[M,N] = A[M,K] B[N,K]^T + bias ----
// block tile 128x128x32, 256 threads = 8 warps (2 m x 4 n), warp tile 64x32.
__global__ __launch_bounds__(256)
void sgemm_tc(const float* __restrict__ A, const float* __restrict__ B,
              const float* __restrict__ bias, float* __restrict__ C,
              int M, int N, int K)
{
    __shared__ uint32_t As[128][36];   // [m][k], tf32 bits, pad 4
    __shared__ uint32_t Bs[128][36];   // [n][k]

    const int tid  = threadIdx.x;
    const int wid  = tid >> 5;
    const int lane = tid & 31;
    const int wm   = (wid & 1) * 64;        // warp m offset in tile
    const int wn   = (wid >> 1) * 32;       // warp n offset in tile
    const int lr   = lane >> 2;             // 0..7
    const int lc   = lane & 3;              // 0..3

    const int m_blk = blockIdx.y * 128;
    const int n_blk = blockIdx.x * 128;

    // gmem load mapping: 1024 float4 per tile side, 4 per thread
    const int gRow = tid >> 1;                // 0..127
    const int gK0  = (tid & 1) * 16;          // 0 or 16

    float4 acc[4][4];
#pragma unroll
    for (int i = 0; i < 4; i++)
#pragma unroll
        for (int j = 0; j < 4; j++) acc[i][j] = make_float4(0.f, 0.f, 0.f, 0.f);

    const float* Ag = A + (size_t)(m_blk + gRow) * K + gK0;
    const float* Bg = B + (size_t)(n_blk + gRow) * K + gK0;

    for (int kt = 0; kt < K; kt += 32) {
        // global -> shared (convert to tf32 bits)
#pragma unroll
        for (int p = 0; p < 4; p++) {
            float4 av = *(const float4*)(Ag + kt + p * 4);
            float4 bv = *(const float4*)(Bg + kt + p * 4);
            int k = gK0 + p * 4;
            As[gRow][k + 0] = f2tf32(av.x); As[gRow][k + 1] = f2tf32(av.y);
            As[gRow][k + 2] = f2tf32(av.z); As[gRow][k + 3] = f2tf32(av.w);
            Bs[gRow][k + 0] = f2tf32(bv.x); Bs[gRow][k + 1] = f2tf32(bv.y);
            Bs[gRow][k + 2] = f2tf32(bv.z); Bs[gRow][k + 3] = f2tf32(bv.w);
        }
        __syncthreads();

#pragma unroll
        for (int ks = 0; ks < 4; ks++) {
            const int k0 = ks * 8;
            uint32_t af[4][4], bf[4][2];
#pragma unroll
            for (int im = 0; im < 4; im++) {
                const int r = wm + im * 16 + lr;
                af[im][0] = As[r    ][k0 + lc];
                af[im][1] = As[r + 8][k0 + lc];
                af[im][2] = As[r    ][k0 + lc + 4];
                af[im][3] = As[r + 8][k0 + lc + 4];
            }
#pragma unroll
            for (int in = 0; in < 4; in++) {
                const int n = wn + in * 8 + lr;
                bf[in][0] = Bs[n][k0 + lc];
                bf[in][1] = Bs[n][k0 + lc + 4];
            }
#pragma unroll
            for (int im = 0; im < 4; im++)
#pragma unroll
                for (int in = 0; in < 4; in++)
                    mma_tf32(acc[im][in], af[im][0], af[im][1], af[im][2], af[im][3],
                             bf[in][0], bf[in][1]);
        }
        __syncthreads();
    }

    // epilogue: D fragment mapping c0,c1 -> (row=lr, col=2*lc), c2,c3 -> row+8
#pragma unroll
    for (int im = 0; im < 4; im++) {
        const int r0 = m_blk + wm + im * 16 + lr;
#pragma unroll
        for (int in = 0; in < 4; in++) {
            const int c0 = n_blk + wn + in * 8 + 2 * lc;
            float2 bia = *(const float2*)&bias[c0];
            float* Cp0 = C + (size_t)r0 * N + c0;
            float* Cp1 = C + (size_t)(r0 + 8) * N + c0;
            Cp0[0] = acc[im][in].x + bia.x;
            Cp0[1] = acc[im][in].y + bia.y;
            Cp1[0] = acc[im][in].z + bia.x;
            Cp1[1] = acc[im][in].w + bia.y;
        }
    }
}

// ---------------- lambda scalar ----------------
__global__ void lambda_kernel(const float* __restrict__ q1, const float* __restrict__ k1,
                              const float* __restrict__ q2, const float* __restrict__ k2)
{
    const int tid = threadIdx.x;   // 128 threads
    float p1 = q1[tid] * k1[tid];
    float p2 = q2[tid] * k2[tid];
#pragma unroll
    for (int m = 16; m; m >>= 1) {
        p1 += __shfl_xor_sync(0xffffffffu, p1, m);
        p2 += __shfl_xor_sync(0xffffffffu, p2, m);
    }
    __shared__ float s1[4], s2[4];
    if ((tid & 31) == 0) { s1[tid >> 5] = p1; s2[tid >> 5] = p2; }
    __syncthreads();
    if (tid == 0) {
        float a = s1[0] + s1[1] + s1[2] + s1[3];
        float b = s2[0] + s2[1] + s2[2] + s2[3];
        g_lambda = expf(a) - expf(b) + LAMBDA_INIT;
    }
}

// ---------------- causal flash attention (fp32) ----------------
__global__ __launch_bounds__(256)
void diff_attn(const float* __restrict__ qkv,
               float* __restrict__ out1, float* __restrict__ out2)
{
    extern __shared__ float sm[];
    float* Qs   = sm;                 // [128][64]  d-major
    float* KV   = Qs + 128 * 64;      // K: [128][64] d-major, then V: [64][256]
    float* Ps   = KV + 64 * 256;      // [64][64]
    float* mrow = Ps + 64 * 64;       // [64]
    float* lrow = mrow + 64;          // [64]
    float* crow = lrow + 64;          // [64]
    float* tmax = crow + 64;          // [64]
    float* tsum = tmax + 64;          // [64]

    const int tid = threadIdx.x;
    const int qi  = blockIdx.x;
    const int hp  = blockIdx.y;
    const int a   = blockIdx.z;
    const int q0  = qi * 64;
    const int qoff = hp * 256 + a * 128;
    const int koff = HID + qoff;
    const int voff = 2 * HID + hp * 256;
    float* out = a ? out2 : out1;

    for (int i = tid; i < 64 * 32; i += 256) {
        int r = i >> 5; int d = (i & 31) << 2;
        float4 v = *(const float4*)&qkv[(size_t)(q0 + r) * QKV_N + qoff + d];
        Qs[(d + 0) * 64 + r] = v.x; Qs[(d + 1) * 64 + r] = v.y;
        Qs[(d + 2) * 64 + r] = v.z; Qs[(d + 3) * 64 + r] = v.w;
    }
    if (tid < 64) { mrow[tid] = -1e30f; lrow[tid] = 0.f; }

    const int tr = tid >> 4, tc = tid & 15;
    const int r0 = tr * 4, cs0 = tc * 4, cv0 = tc * 16;
    float oacc[4][16];
#pragma unroll
    for (int i = 0; i < 4; i++)
#pragma unroll
        for (int j = 0; j < 16; j++) oacc[i][j] = 0.f;
    __syncthreads();

    const float scale = 0.088388347648318447f;  // 1/sqrt(128)
    const int ntiles = qi + 1;

    for (int t = 0; t < ntiles; t++) {
        const int k0 = t * 64;

        for (int i = tid; i < 64 * 32; i += 256) {
            int c = i >> 5; int d = (i & 31) << 2;
            float4 v = *(const float4*)&qkv[(size_t)(k0 + c) * QKV_N + koff + d];
            KV[(d + 0) * 64 + c] = v.x; KV[(d + 1) * 64 + c] = v.y;
            KV[(d + 2) * 64 + c] = v.z; KV[(d + 3) * 64 + c] = v.w;
        }
        __syncthreads();

        float s4[4][4];
#pragma unroll
        for (int i = 0; i < 4; i++)
#pragma unroll
            for (int j = 0; j < 4; j++) s4[i][j] = 0.f;
#pragma unroll 4
        for (int d = 0; d < 128; d++) {
            float qa[4], kb[4];
            *(float4*)qa = *(const float4*)&Qs[d * 64 + r0];
            *(float4*)kb = *(const float4*)&KV[d * 64 + cs0];
#pragma unroll
            for (int i = 0; i < 4; i++)
#pragma unroll
                for (int j = 0; j < 4; j++)
                    s4[i][j] = fmaf(qa[i], kb[j], s4[i][j]);
        }
        __syncthreads();

        for (int i = tid; i < 64 * 64; i += 256) {
            int j = i >> 6; int e = (i & 63) << 2;
            *(float4*)&KV[j * 256 + e] =
                *(const float4*)&qkv[(size_t)(k0 + j) * QKV_N + voff + e];
        }

        const bool diag = (t == qi);
        float rm[4];
#pragma unroll
        for (int i = 0; i < 4; i++) {
            rm[i] = -1e30f;
#pragma unroll
            for (int j = 0; j < 4; j++) {
                float v = s4[i][j] * scale;
                if (diag && (k0 + cs0 + j) > (q0 + r0 + i)) v = -1e30f;
                s4[i][j] = v;
                rm[i] = fmaxf(rm[i], v);
            }
        }
#pragma unroll
        for (int m = 1; m < 16; m <<= 1)
#pragma unroll
            for (int i = 0; i < 4; i++)
                rm[i] = fmaxf(rm[i], __shfl_xor_sync(0xffffffffu, rm[i], m, 32));
        if (tc == 0) {
            tmax[r0 + 0] = rm[0]; tmax[r0 + 1] = rm[1];
            tmax[r0 + 2] = rm[2]; tmax[r0 + 3] = rm[3];
        }
        __syncthreads();

        if (tid < 64) {
            float mo = mrow[tid];
            float mn = fmaxf(mo, tmax[tid]);
            float c  = __expf(mo - mn);
            mrow[tid] = mn; crow[tid] = c; lrow[tid] *= c;
        }
        __syncthreads();

        float rs[4];
#pragma unroll
        for (int i = 0; i < 4; i++) {
            const float mn = mrow[r0 + i];
            rs[i] = 0.f;
#pragma unroll
            for (int j = 0; j < 4; j++) {
                float p = __expf(s4[i][j] - mn);
                Ps[(r0 + i) * 64 + cs0 + j] = p;
                rs[i] += p;
            }
            const float c = crow[r0 + i];
#pragma unroll
            for (int e = 0; e < 16; e++) oacc[i][e] *= c;
        }
#pragma unroll
        for (int m = 1; m < 16; m <<= 1)
#pragma unroll
            for (int i = 0; i < 4; i++)
                rs[i] += __shfl_xor_sync(0xffffffffu, rs[i], m, 32);
        if (tc == 0) {
            tsum[r0 + 0] = rs[0]; tsum[r0 + 1] = rs[1];
            tsum[r0 + 2] = rs[2]; tsum[r0 + 3] = rs[3];
        }
        __syncthreads();
        if (tid < 64) lrow[tid] += tsum[tid];

#pragma unroll 2
        for (int j = 0; j < 64; j++) {
            float p0 = Ps[(r0 + 0) * 64 + j];
            float p1 = Ps[(r0 + 1) * 64 + j];
            float p2 = Ps[(r0 + 2) * 64 + j];
            float p3 = Ps[(r0 + 3) * 64 + j];
            const float* vp = &KV[j * 256 + cv0];
#pragma unroll
            for (int e4 = 0; e4 < 4; e4++) {
                float4 vv = *(const float4*)&vp[e4 * 4];
                oacc[0][e4 * 4 + 0] = fmaf(p0, vv.x, oacc[0][e4 * 4 + 0]);
                oacc[0][e4 * 4 + 1] = fmaf(p0, vv.y, oacc[0][e4 * 4 + 1]);
                oacc[0][e4 * 4 + 2] = fmaf(p0, vv.z, oacc[0][e4 * 4 + 2]);
                oacc[0][e4 * 4 + 3] = fmaf(p0, vv.w, oacc[0][e4 * 4 + 3]);
                oacc[1][e4 * 4 + 0] = fmaf(p1, vv.x, oacc[1][e4 * 4 + 0]);
                oacc[1][e4 * 4 + 1] = fmaf(p1, vv.y, oacc[1][e4 * 4 + 1]);
                oacc[1][e4 * 4 + 2] = fmaf(p1, vv.z, oacc[1][e4 * 4 + 2]);
                oacc[1][e4 * 4 + 3] = fmaf(p1, vv.w, oacc[1][e4 * 4 + 3]);
                oacc[2][e4 * 4 + 0] = fmaf(p2, vv.x, oacc[2][e4 * 4 + 0]);
                oacc[2][e4 * 4 + 1] = fmaf(p2, vv.y, oacc[2][e4 * 4 + 1]);
                oacc[2][e4 * 4 + 2] = fmaf(p2, vv.z, oacc[2][e4 * 4 + 2]);
                oacc[2][e4 * 4 + 3] = fmaf(p2, vv.w, oacc[2][e4 * 4 + 3]);
                oacc[3][e4 * 4 + 0] = fmaf(p3, vv.x, oacc[3][e4 * 4 + 0]);
                oacc[3][e4 * 4 + 1] = fmaf(p3, vv.y, oacc[3][e4 * 4 + 1]);
                oacc[3][e4 * 4 + 2] = fmaf(p3, vv.z, oacc[3][e4 * 4 + 2]);
                oacc[3][e4 * 4 + 3] = fmaf(p3, vv.w, oacc[3][e4 * 4 + 3]);
            }
        }
        __syncthreads();
    }

#pragma unroll
    for (int i = 0; i < 4; i++) {
        const float inv = 1.f / lrow[r0 + i];
        float* op = out + (size_t)(q0 + r0 + i) * HID + hp * 256 + cv0;
#pragma unroll
        for (int e = 0; e < 16; e++) op[e] = oacc[i][e] * inv;
    }
}

// ---------------- combine (attn1 - lambda*attn2) + RMSNorm ----------------
__global__ __launch_bounds__(256)
void combine_rms(const float* __restrict__ a1, const float* __restrict__ a2,
                 const float* __restrict__ w, float* __restrict__ x)
{
    const int s = blockIdx.x, hp = blockIdx.y, e = threadIdx.x;
    const size_t idx = (size_t)s * HID + hp * 256 + e;
    const float lam = g_lambda;
    const float v = a1[idx] - lam * a2[idx];
    float ss = v * v;
#pragma unroll
    for (int m = 16; m; m >>= 1) ss += __shfl_xor_sync(0xffffffffu, ss, m);
    __shared__ float red[8];
    if ((e & 31) == 0) red[e >> 5] = ss;
    __syncthreads();
    float tot = 0.f;
#pragma unroll
    for (int i = 0; i < 8; i++) tot += red[i];
    const float r = rsqrtf(tot * (1.f / 256.f) + EPS);
    x[idx] = w[e] * v * r * (1.f - LAMBDA_INIT);
}

// ---------------- launch ----------------
extern "C" void kernel_launch(void* const* d_in, const int* in_sizes, int n_in,
                              void* d_out, int out_size)
{
    const float* hidden = (const float*)d_in[0];
    const float* Wqkv_w = (const float*)d_in[1];
    const float* Wqkv_b = (const float*)d_in[2];
    const float* out_w  = (const float*)d_in[3];
    const float* out_b  = (const float*)d_in[4];
    const float* lq1    = (const float*)d_in[5];
    const float* lk1    = (const float*)d_in[6];
    const float* lq2    = (const float*)d_in[7];
    const float* lk2    = (const float*)d_in[8];
    const float* subln  = (const float*)d_in[9];
    float* out = (float*)d_out;

    float *qkv, *a1, *a2, *x;
    cudaGetSymbolAddress((void**)&qkv, g_qkv);
    cudaGetSymbolAddress((void**)&a1,  g_attn1);
    cudaGetSymbolAddress((void**)&a2,  g_attn2);
    cudaGetSymbolAddress((void**)&x,   g_x);

    const int SMEM_ATT = (128 * 64 + 64 * 256 + 64 * 64 + 5 * 64) * (int)sizeof(float);
    cudaFuncSetAttribute(diff_attn, cudaFuncAttributeMaxDynamicSharedMemorySize, SMEM_ATT);

    // 1. lambda scalar
    lambda_kernel<<<1, 128>>>(lq1, lk1, lq2, lk2);

    // 2. QKV projection (tensor cores, tf32)
    sgemm_tc<<<dim3(QKV_N / 128, S_LEN / 128), 256>>>(
        hidden, Wqkv_w, Wqkv_b, qkv, S_LEN, QKV_N, HID);

    // 3. dual causal flash attention
    diff_attn<<<dim3(S_LEN / 64, HP_N, 2), 256, SMEM_ATT>>>(qkv, a1, a2);

    // 4. combine + rmsnorm
    combine_rms<<<dim3(S_LEN, HP_N), 256>>>(a1, a2, subln, x);

    // 5. output projection (tensor cores, tf32)
    sgemm_tc<<<dim3(HID / 128, S_LEN / 128), 256>>>(
        x, out_w, out_b, out, S_LEN, HID, HID);
}